// round 2
// baseline (speedup 1.0000x reference)
#include <cuda_runtime.h>
#include <cuda_bf16.h>
#include <cstdint>

// ---------------------------------------------------------------------------
// Problem shape (fixed by dataset): N=50000, E=1.6M, D=128, A=4, H=128
// ---------------------------------------------------------------------------
#define NMAX 50048          // 391 tiles of 128
#define DDIM 128

// Scratch (no cudaMalloc allowed anywhere)
__device__ float g_P   [(size_t)NMAX * DDIM];
__device__ float g_pool[(size_t)NMAX * DDIM];
__device__ float g_x1  [(size_t)NMAX * DDIM];
__device__ __nv_bfloat16 g_Wt[4 * 128 * 128];   // transposed bf16 weights

// ---------------------------------------------------------------------------
// helpers
// ---------------------------------------------------------------------------
__device__ __forceinline__ uint32_t smem_u32(const void* p) {
    uint32_t a;
    asm("{ .reg .u64 t; cvta.to.shared.u64 t, %1; cvt.u32.u64 %0, t; }"
        : "=r"(a) : "l"(p));
    return a;
}
__device__ __forceinline__ void ldsm_x4(uint32_t& r0, uint32_t& r1,
                                        uint32_t& r2, uint32_t& r3, uint32_t a) {
    asm volatile("ldmatrix.sync.aligned.m8n8.x4.shared.b16 {%0,%1,%2,%3}, [%4];"
                 : "=r"(r0), "=r"(r1), "=r"(r2), "=r"(r3) : "r"(a));
}
__device__ __forceinline__ void ldsm_x2(uint32_t& r0, uint32_t& r1, uint32_t a) {
    asm volatile("ldmatrix.sync.aligned.m8n8.x2.shared.b16 {%0,%1}, [%2];"
                 : "=r"(r0), "=r"(r1) : "r"(a));
}
__device__ __forceinline__ void mma_bf16(float* c, const uint32_t* a, const uint32_t* b) {
    asm volatile(
        "mma.sync.aligned.m16n8k16.row.col.f32.bf16.bf16.f32 "
        "{%0,%1,%2,%3}, {%4,%5,%6,%7}, {%8,%9}, {%0,%1,%2,%3};"
        : "+f"(c[0]), "+f"(c[1]), "+f"(c[2]), "+f"(c[3])
        : "r"(a[0]), "r"(a[1]), "r"(a[2]), "r"(a[3]), "r"(b[0]), "r"(b[1]));
}

// ---------------------------------------------------------------------------
// prep: Wt[w][n][k] = bf16(W_w[k][n]), k,n in [0,128)  (only first 128 rows of
// Wb are used; rows 128..131 are the add_info weights, consumed in fp32)
// ---------------------------------------------------------------------------
__global__ void __launch_bounds__(256)
prep_w(const float* __restrict__ W0, const float* __restrict__ W1,
       const float* __restrict__ W2, const float* __restrict__ W3,
       __nv_bfloat16* __restrict__ Wt)
{
    const float* Ws[4] = {W0, W1, W2, W3};
    const float* W = Ws[blockIdx.y];
    __nv_bfloat16* dst = Wt + (size_t)blockIdx.y * 16384;
    int i = blockIdx.x * 256 + threadIdx.x;       // 0..16383
    int n = i >> 7, k = i & 127;
    dst[n * 128 + k] = __float2bfloat16(W[k * 128 + n]);
}

// ---------------------------------------------------------------------------
// GEMM: out[M,128] = A[M,128] @ W (B = W^T supplied as bf16 [n][k])
//   mode 0: Pout = A@W + bias
//   mode 1: Pout = resid + A@W + bias
// mma.sync m16n8k16 bf16, fp32 accum. CTA = 128x128 tile, 8 warps (2x4),
// each warp 64x32 (4 m-tiles x 4 n-tiles), K=128 (8 k-steps).
// ---------------------------------------------------------------------------
#define AS_STRIDE 136                         // bf16 elems per smem row (pad 8)
static constexpr int SMEM_AB = 128 * AS_STRIDE * 2;       // 34816 B each
static constexpr int SMEM_GEMM_TOTAL = 2 * SMEM_AB;       // 69632 B

__global__ void __launch_bounds__(256, 1)
gemm128(const float* __restrict__ A, const __nv_bfloat16* __restrict__ Wt,
        const float* __restrict__ bias, const float* __restrict__ resid,
        float* __restrict__ Pout, int M, int mode)
{
    extern __shared__ char smem[];
    uint32_t sA = smem_u32(smem);
    uint32_t sB = sA + SMEM_AB;
    int tid = threadIdx.x, lane = tid & 31, wid = tid >> 5;
    int wm = wid & 1, wn = wid >> 1;
    int g = lane >> 2, tg = lane & 3;
    int tile0 = blockIdx.x * 128;

    // Fill A tile: fp32 -> bf16, row stride AS_STRIDE
    for (int p = tid; p < 8192; p += 256) {
        int r = p >> 6, c2 = (p & 63) << 1;
        int gr = tile0 + r;
        float2 v = make_float2(0.f, 0.f);
        if (gr < M) v = *reinterpret_cast<const float2*>(A + (size_t)gr * 128 + c2);
        __nv_bfloat162 b2 = __float22bfloat162_rn(v);
        *reinterpret_cast<uint32_t*>(smem + (r * AS_STRIDE + c2) * 2) =
            *reinterpret_cast<const uint32_t*>(&b2);
    }
    // Fill B tile: coalesced u32 copies from pre-transposed bf16 W
    {
        const uint32_t* src = reinterpret_cast<const uint32_t*>(Wt);
        for (int p = tid; p < 8192; p += 256) {
            int n = p >> 6, c = p & 63;          // c = u32 index within row
            *reinterpret_cast<uint32_t*>(smem + SMEM_AB + (n * AS_STRIDE + c * 2) * 2) =
                src[p];
        }
    }
    __syncthreads();

    float acc[4][4][4];
#pragma unroll
    for (int mt = 0; mt < 4; mt++)
#pragma unroll
        for (int nt = 0; nt < 4; nt++)
#pragma unroll
            for (int j = 0; j < 4; j++) acc[mt][nt][j] = 0.f;

    int aRow = wm * 64 + (lane & 15);
    int aCol = (lane >> 4) * 8;
    int bRow = wn * 32 + (lane & 7);
    int bCol = ((lane >> 3) & 1) * 8;

#pragma unroll
    for (int k = 0; k < 8; k++) {
        uint32_t a[4][4], b[4][2];
#pragma unroll
        for (int mt = 0; mt < 4; mt++)
            ldsm_x4(a[mt][0], a[mt][1], a[mt][2], a[mt][3],
                    sA + ((aRow + mt * 16) * AS_STRIDE + k * 16 + aCol) * 2);
#pragma unroll
        for (int nt = 0; nt < 4; nt++)
            ldsm_x2(b[nt][0], b[nt][1],
                    sB + ((bRow + nt * 8) * AS_STRIDE + k * 16 + bCol) * 2);
#pragma unroll
        for (int mt = 0; mt < 4; mt++)
#pragma unroll
            for (int nt = 0; nt < 4; nt++)
                mma_bf16(acc[mt][nt], a[mt], b[nt]);
    }

    // Epilogue: c0,c1 -> row g, cols tg*2,+1 ; c2,c3 -> row g+8
#pragma unroll
    for (int mt = 0; mt < 4; mt++) {
        int r0 = tile0 + wm * 64 + mt * 16 + g;
#pragma unroll
        for (int nt = 0; nt < 4; nt++) {
            int c0 = wn * 32 + nt * 8 + tg * 2;
            float b0 = __ldg(bias + c0), b1 = __ldg(bias + c0 + 1);
            if (r0 < M) {
                float v0 = acc[mt][nt][0] + b0, v1 = acc[mt][nt][1] + b1;
                if (mode == 1) {
                    float2 rv = *reinterpret_cast<const float2*>(
                        resid + (size_t)r0 * 128 + c0);
                    v0 += rv.x; v1 += rv.y;
                }
                *reinterpret_cast<float2*>(Pout + (size_t)r0 * 128 + c0) =
                    make_float2(v0, v1);
            }
            if (r0 + 8 < M) {
                float v0 = acc[mt][nt][2] + b0, v1 = acc[mt][nt][3] + b1;
                if (mode == 1) {
                    float2 rv = *reinterpret_cast<const float2*>(
                        resid + (size_t)(r0 + 8) * 128 + c0);
                    v0 += rv.x; v1 += rv.y;
                }
                *reinterpret_cast<float2*>(Pout + (size_t)(r0 + 8) * 128 + c0) =
                    make_float2(v0, v1);
            }
        }
    }
}

// ---------------------------------------------------------------------------
// Edge kernel: h[c] = P[idx_e][c] + add_e @ Wadd[:,c]; relu folded into
// zero-init running max; segment max flushed via atomicMax on uint (valid
// since relu output >= 0 and pool zero-initialized).
// One warp = 128 contiguous edges; thread owns 4 columns.
// ---------------------------------------------------------------------------
#define EDGE_SPAN 128

__global__ void __launch_bounds__(256)
edge_kernel(const float* __restrict__ P, const float4* __restrict__ add,
            const int* __restrict__ nidx, const int* __restrict__ segs,
            const float* __restrict__ Wadd, float* __restrict__ pool, int E)
{
    int gw = blockIdx.x * 8 + (threadIdx.x >> 5);
    int lane = threadIdx.x & 31;
    long e0 = (long)gw * EDGE_SPAN;
    if (e0 >= E) return;
    long e1 = e0 + EDGE_SPAN;
    if (e1 > E) e1 = E;

    int cb = lane * 4;
    float wa[4][4];
#pragma unroll
    for (int a = 0; a < 4; a++)
#pragma unroll
        for (int j = 0; j < 4; j++)
            wa[a][j] = __ldg(Wadd + a * 128 + cb + j);

    float m0 = 0.f, m1 = 0.f, m2 = 0.f, m3 = 0.f;
    int cur = __ldg(segs + e0);

#define EDGE_FLUSH() do { \
    unsigned* _d = reinterpret_cast<unsigned*>(pool + (size_t)cur * 128 + cb); \
    atomicMax(_d + 0, __float_as_uint(m0)); \
    atomicMax(_d + 1, __float_as_uint(m1)); \
    atomicMax(_d + 2, __float_as_uint(m2)); \
    atomicMax(_d + 3, __float_as_uint(m3)); \
    m0 = m1 = m2 = m3 = 0.f; } while (0)

    for (long e = e0; e < e1; e += 2) {
        int    sgA = __ldg(segs + e);
        int    idA = __ldg(nidx + e);
        float4 adA = __ldg(add + e);
        float4 pA  = __ldg(reinterpret_cast<const float4*>(P + (size_t)idA * 128) + lane);
        bool   has2 = (e + 1 < e1);
        int    sgB = 0;
        float4 adB = make_float4(0.f, 0.f, 0.f, 0.f);
        float4 pB  = make_float4(0.f, 0.f, 0.f, 0.f);
        if (has2) {
            sgB = __ldg(segs + e + 1);
            int idB = __ldg(nidx + e + 1);
            adB = __ldg(add + e + 1);
            pB  = __ldg(reinterpret_cast<const float4*>(P + (size_t)idB * 128) + lane);
        }

        if (sgA != cur) { EDGE_FLUSH(); cur = sgA; }
        m0 = fmaxf(m0, pA.x + adA.x*wa[0][0] + adA.y*wa[1][0] + adA.z*wa[2][0] + adA.w*wa[3][0]);
        m1 = fmaxf(m1, pA.y + adA.x*wa[0][1] + adA.y*wa[1][1] + adA.z*wa[2][1] + adA.w*wa[3][1]);
        m2 = fmaxf(m2, pA.z + adA.x*wa[0][2] + adA.y*wa[1][2] + adA.z*wa[2][2] + adA.w*wa[3][2]);
        m3 = fmaxf(m3, pA.w + adA.x*wa[0][3] + adA.y*wa[1][3] + adA.z*wa[2][3] + adA.w*wa[3][3]);

        if (has2) {
            if (sgB != cur) { EDGE_FLUSH(); cur = sgB; }
            m0 = fmaxf(m0, pB.x + adB.x*wa[0][0] + adB.y*wa[1][0] + adB.z*wa[2][0] + adB.w*wa[3][0]);
            m1 = fmaxf(m1, pB.y + adB.x*wa[0][1] + adB.y*wa[1][1] + adB.z*wa[2][1] + adB.w*wa[3][1]);
            m2 = fmaxf(m2, pB.z + adB.x*wa[0][2] + adB.y*wa[1][2] + adB.z*wa[2][2] + adB.w*wa[3][2]);
            m3 = fmaxf(m3, pB.w + adB.x*wa[0][3] + adB.y*wa[1][3] + adB.z*wa[2][3] + adB.w*wa[3][3]);
        }
    }
    EDGE_FLUSH();
#undef EDGE_FLUSH
}

// ---------------------------------------------------------------------------
__global__ void __launch_bounds__(256)
zero_kernel(float4* __restrict__ p, int n4)
{
    int i = blockIdx.x * blockDim.x + threadIdx.x;
    if (i < n4) p[i] = make_float4(0.f, 0.f, 0.f, 0.f);
}

// out[r] = dot(x[r], Wf) + bf    (one warp per row)
__global__ void __launch_bounds__(256)
head_kernel(const float* __restrict__ x, const float* __restrict__ Wf,
            const float* __restrict__ bf, float* __restrict__ out, int N)
{
    int wid = threadIdx.x >> 5, lane = threadIdx.x & 31;
    int row = blockIdx.x * 8 + wid;
    if (row >= N) return;
    float4 xv = *reinterpret_cast<const float4*>(x + (size_t)row * 128 + lane * 4);
    float4 wv = __ldg(reinterpret_cast<const float4*>(Wf) + lane);
    float s = xv.x * wv.x + xv.y * wv.y + xv.z * wv.z + xv.w * wv.w;
#pragma unroll
    for (int o = 16; o > 0; o >>= 1) s += __shfl_xor_sync(0xFFFFFFFFu, s, o);
    if (lane == 0) out[row] = s + __ldg(bf);
}

// ---------------------------------------------------------------------------
extern "C" void kernel_launch(void* const* d_in, const int* in_sizes, int n_in,
                              void* d_out, int out_size)
{
    const float* interp = (const float*)d_in[0];
    const float* add    = (const float*)d_in[1];
    const int*   nidx   = (const int*)d_in[2];
    const int*   segs   = (const int*)d_in[3];
    const float* Wb0 = (const float*)d_in[4];
    const float* bb0 = (const float*)d_in[5];
    const float* Wo0 = (const float*)d_in[6];
    const float* bo0 = (const float*)d_in[7];
    const float* Wb1 = (const float*)d_in[8];
    const float* bb1 = (const float*)d_in[9];
    const float* Wo1 = (const float*)d_in[10];
    const float* bo1 = (const float*)d_in[11];
    const float* Wf  = (const float*)d_in[12];
    const float* bf  = (const float*)d_in[13];
    float* out = (float*)d_out;

    int N = in_sizes[0] / 128;
    int E = in_sizes[2];

    float *P, *pool, *x1;
    __nv_bfloat16* Wt;
    cudaGetSymbolAddress((void**)&P, g_P);
    cudaGetSymbolAddress((void**)&pool, g_pool);
    cudaGetSymbolAddress((void**)&x1, g_x1);
    cudaGetSymbolAddress((void**)&Wt, g_Wt);

    cudaFuncSetAttribute(gemm128, cudaFuncAttributeMaxDynamicSharedMemorySize,
                         SMEM_GEMM_TOTAL);

    int gtiles = (N + 127) / 128;
    int n4 = N * 32;
    int zgrid = (n4 + 255) / 256;
    int egrid = ((E + EDGE_SPAN - 1) / EDGE_SPAN + 7) / 8;

    // One-time (per launch) weight transpose + bf16 convert
    prep_w<<<dim3(64, 4), 256>>>(Wb0, Wo0, Wb1, Wo1, Wt);

    // Block 0
    zero_kernel<<<zgrid, 256>>>((float4*)pool, n4);
    gemm128<<<gtiles, 256, SMEM_GEMM_TOTAL>>>(interp, Wt + 0 * 16384, bb0,
                                              nullptr, P, N, 0);
    edge_kernel<<<egrid, 256>>>(P, (const float4*)add, nidx, segs,
                                Wb0 + 128 * 128, pool, E);
    gemm128<<<gtiles, 256, SMEM_GEMM_TOTAL>>>(pool, Wt + 1 * 16384, bo0,
                                              interp, x1, N, 1);
    // Block 1
    zero_kernel<<<zgrid, 256>>>((float4*)pool, n4);
    gemm128<<<gtiles, 256, SMEM_GEMM_TOTAL>>>(x1, Wt + 2 * 16384, bb1,
                                              nullptr, P, N, 0);
    edge_kernel<<<egrid, 256>>>(P, (const float4*)add, nidx, segs,
                                Wb1 + 128 * 128, pool, E);
    gemm128<<<gtiles, 256, SMEM_GEMM_TOTAL>>>(pool, Wt + 3 * 16384, bo1,
                                              x1, P, N, 1);          // xf -> P
    // Final head
    head_kernel<<<(N + 7) / 8, 256>>>(P, Wf, bf, out, N);
}

// round 3
// speedup vs baseline: 1.0037x; 1.0037x over previous
#include <cuda_runtime.h>
#include <cuda_bf16.h>
#include <cstdint>

// ---------------------------------------------------------------------------
// Problem shape (fixed by dataset): N=50000, E=1.6M, D=128, A=4, H=128
// ---------------------------------------------------------------------------
#define NMAX 50048          // 391 tiles of 128
#define DDIM 128

// Scratch (no cudaMalloc allowed anywhere)
__device__ __nv_bfloat16 g_P[(size_t)NMAX * DDIM];      // bf16 activations
__device__ float g_pool[(size_t)NMAX * DDIM];
__device__ float g_x1  [(size_t)NMAX * DDIM];
__device__ __nv_bfloat16 g_Wt[4 * 128 * 128];           // transposed bf16 weights

// ---------------------------------------------------------------------------
// helpers
// ---------------------------------------------------------------------------
__device__ __forceinline__ uint32_t smem_u32(const void* p) {
    uint32_t a;
    asm("{ .reg .u64 t; cvta.to.shared.u64 t, %1; cvt.u32.u64 %0, t; }"
        : "=r"(a) : "l"(p));
    return a;
}
__device__ __forceinline__ void ldsm_x4(uint32_t& r0, uint32_t& r1,
                                        uint32_t& r2, uint32_t& r3, uint32_t a) {
    asm volatile("ldmatrix.sync.aligned.m8n8.x4.shared.b16 {%0,%1,%2,%3}, [%4];"
                 : "=r"(r0), "=r"(r1), "=r"(r2), "=r"(r3) : "r"(a));
}
__device__ __forceinline__ void ldsm_x2(uint32_t& r0, uint32_t& r1, uint32_t a) {
    asm volatile("ldmatrix.sync.aligned.m8n8.x2.shared.b16 {%0,%1}, [%2];"
                 : "=r"(r0), "=r"(r1) : "r"(a));
}
__device__ __forceinline__ void mma_bf16(float* c, const uint32_t* a, const uint32_t* b) {
    asm volatile(
        "mma.sync.aligned.m16n8k16.row.col.f32.bf16.bf16.f32 "
        "{%0,%1,%2,%3}, {%4,%5,%6,%7}, {%8,%9}, {%0,%1,%2,%3};"
        : "+f"(c[0]), "+f"(c[1]), "+f"(c[2]), "+f"(c[3])
        : "r"(a[0]), "r"(a[1]), "r"(a[2]), "r"(a[3]), "r"(b[0]), "r"(b[1]));
}

// ---------------------------------------------------------------------------
// prep: Wt[w][n][k] = bf16(W_w[k][n])  (first 128 rows of Wb; rows 128..131
// are the add_info weights, consumed in fp32->bf16x2 inside edge kernel)
// ---------------------------------------------------------------------------
__global__ void __launch_bounds__(256)
prep_w(const float* __restrict__ W0, const float* __restrict__ W1,
       const float* __restrict__ W2, const float* __restrict__ W3,
       __nv_bfloat16* __restrict__ Wt)
{
    const float* Ws[4] = {W0, W1, W2, W3};
    const float* W = Ws[blockIdx.y];
    __nv_bfloat16* dst = Wt + (size_t)blockIdx.y * 16384;
    int i = blockIdx.x * 256 + threadIdx.x;       // 0..16383
    int n = i >> 7, k = i & 127;
    dst[n * 128 + k] = __float2bfloat16(W[k * 128 + n]);
}

// ---------------------------------------------------------------------------
// GEMM: A[M,128](fp32) @ W  (B = W^T as bf16 [n][k]),  fp32 accum.
//   mode 0: Pb = bf16(A@W + bias); also zero pool rows   (pre-edge)
//   mode 1: Xout = resid + A@W + bias                    (fp32, block-0 proj)
//   mode 2: out  = (resid + A@W + bias) @ Wf + bf        (final head fused)
// CTA = 128x128 tile, 8 warps (2x4), warp = 64x32, K=128 (8 k-steps).
// ---------------------------------------------------------------------------
#define AS_STRIDE 136                         // bf16 elems per smem row (pad 8)
static constexpr int SMEM_AB = 128 * AS_STRIDE * 2;       // 34816 B each
static constexpr int SMEM_GEMM_TOTAL = 2 * SMEM_AB;       // 69632 B

__global__ void __launch_bounds__(256, 1)
gemm128(const float* __restrict__ A, const __nv_bfloat16* __restrict__ Wt,
        const float* __restrict__ bias, const float* __restrict__ resid,
        __nv_bfloat16* __restrict__ Pb, float* __restrict__ Xout,
        float* __restrict__ pool,
        const float* __restrict__ Wf, const float* __restrict__ bfp,
        float* __restrict__ out, int M, int mode)
{
    extern __shared__ char smem[];
    uint32_t sA = smem_u32(smem);
    uint32_t sB = sA + SMEM_AB;
    int tid = threadIdx.x, lane = tid & 31, wid = tid >> 5;
    int wm = wid & 1, wn = wid >> 1;
    int g = lane >> 2, tg = lane & 3;
    int tile0 = blockIdx.x * 128;

    // Fill A tile: fp32 -> bf16, row stride AS_STRIDE
    for (int p = tid; p < 8192; p += 256) {
        int r = p >> 6, c2 = (p & 63) << 1;
        int gr = tile0 + r;
        float2 v = make_float2(0.f, 0.f);
        if (gr < M) v = *reinterpret_cast<const float2*>(A + (size_t)gr * 128 + c2);
        __nv_bfloat162 b2 = __floats2bfloat162_rn(v.x, v.y);
        *reinterpret_cast<uint32_t*>(smem + (r * AS_STRIDE + c2) * 2) =
            *reinterpret_cast<const uint32_t*>(&b2);
    }
    // Fill B tile: coalesced u32 copies from pre-transposed bf16 W
    {
        const uint32_t* src = reinterpret_cast<const uint32_t*>(Wt);
        for (int p = tid; p < 8192; p += 256) {
            int n = p >> 6, c = p & 63;
            *reinterpret_cast<uint32_t*>(smem + SMEM_AB + (n * AS_STRIDE + c * 2) * 2) =
                src[p];
        }
    }
    // mode 0: zero the pool rows for this tile (fused, replaces zero_kernel)
    if (mode == 0) {
        for (int idx = tid; idx < 4096; idx += 256) {
            int r = idx >> 5, c4 = idx & 31;
            if (tile0 + r < M)
                *reinterpret_cast<float4*>(pool + (size_t)(tile0 + r) * 128 + c4 * 4) =
                    make_float4(0.f, 0.f, 0.f, 0.f);
        }
    }
    __syncthreads();

    float acc[4][4][4];
#pragma unroll
    for (int mt = 0; mt < 4; mt++)
#pragma unroll
        for (int nt = 0; nt < 4; nt++)
#pragma unroll
            for (int j = 0; j < 4; j++) acc[mt][nt][j] = 0.f;

    int aRow = wm * 64 + (lane & 15);
    int aCol = (lane >> 4) * 8;
    int bRow = wn * 32 + (lane & 7);
    int bCol = ((lane >> 3) & 1) * 8;

#pragma unroll
    for (int k = 0; k < 8; k++) {
        uint32_t a[4][4], b[4][2];
#pragma unroll
        for (int mt = 0; mt < 4; mt++)
            ldsm_x4(a[mt][0], a[mt][1], a[mt][2], a[mt][3],
                    sA + ((aRow + mt * 16) * AS_STRIDE + k * 16 + aCol) * 2);
#pragma unroll
        for (int nt = 0; nt < 4; nt++)
            ldsm_x2(b[nt][0], b[nt][1],
                    sB + ((bRow + nt * 8) * AS_STRIDE + k * 16 + bCol) * 2);
#pragma unroll
        for (int mt = 0; mt < 4; mt++)
#pragma unroll
            for (int nt = 0; nt < 4; nt++)
                mma_bf16(acc[mt][nt], a[mt], b[nt]);
    }

    // head-partial smem (mode 2): [128 rows][16 slots], stride 17 (pad)
    float* hp = reinterpret_cast<float*>(smem);
    if (mode == 2) __syncthreads();          // done reading A/B smem

    // Epilogue: acc[..][0,1] -> row g cols tg*2,+1 ; [2,3] -> row g+8
#pragma unroll
    for (int mt = 0; mt < 4; mt++) {
        int rl = wm * 64 + mt * 16 + g;              // local row
        int r0 = tile0 + rl;
        float plo = 0.f, phi = 0.f;                  // head partials (mode 2)
#pragma unroll
        for (int nt = 0; nt < 4; nt++) {
            int c0 = wn * 32 + nt * 8 + tg * 2;
            float b0 = __ldg(bias + c0), b1 = __ldg(bias + c0 + 1);
            float v0 = acc[mt][nt][0] + b0, v1 = acc[mt][nt][1] + b1;
            float u0 = acc[mt][nt][2] + b0, u1 = acc[mt][nt][3] + b1;
            if (mode != 0) {
                if (r0 < M) {
                    float2 rv = *reinterpret_cast<const float2*>(
                        resid + (size_t)r0 * 128 + c0);
                    v0 += rv.x; v1 += rv.y;
                }
                if (r0 + 8 < M) {
                    float2 rv = *reinterpret_cast<const float2*>(
                        resid + (size_t)(r0 + 8) * 128 + c0);
                    u0 += rv.x; u1 += rv.y;
                }
            }
            if (mode == 0) {
                if (r0 < M) {
                    __nv_bfloat162 o = __floats2bfloat162_rn(v0, v1);
                    *reinterpret_cast<uint32_t*>(Pb + (size_t)r0 * 128 + c0) =
                        *reinterpret_cast<uint32_t*>(&o);
                }
                if (r0 + 8 < M) {
                    __nv_bfloat162 o = __floats2bfloat162_rn(u0, u1);
                    *reinterpret_cast<uint32_t*>(Pb + (size_t)(r0 + 8) * 128 + c0) =
                        *reinterpret_cast<uint32_t*>(&o);
                }
            } else if (mode == 1) {
                if (r0 < M)
                    *reinterpret_cast<float2*>(Xout + (size_t)r0 * 128 + c0) =
                        make_float2(v0, v1);
                if (r0 + 8 < M)
                    *reinterpret_cast<float2*>(Xout + (size_t)(r0 + 8) * 128 + c0) =
                        make_float2(u0, u1);
            } else {
                float w0 = __ldg(Wf + c0), w1 = __ldg(Wf + c0 + 1);
                plo += v0 * w0 + v1 * w1;
                phi += u0 * w0 + u1 * w1;
            }
        }
        if (mode == 2) {
            int slot = wn * 4 + tg;
            hp[rl * 17 + slot] = plo;
            hp[(rl + 8) * 17 + slot] = phi;
        }
    }

    if (mode == 2) {
        __syncthreads();
        if (tid < 128) {
            int r0 = tile0 + tid;
            if (r0 < M) {
                float s = 0.f;
#pragma unroll
                for (int j = 0; j < 16; j++) s += hp[tid * 17 + j];
                out[r0] = s + __ldg(bfp);
            }
        }
    }
}

// ---------------------------------------------------------------------------
// Edge kernel (bf16x2): h2 = P2[idx_e] + add_e @ Wadd (packed HFMA2), relu
// folded into zero-init running max (HMAX2); segment max flushed via fp32
// atomicMax on uint (valid: relu output >= 0, pool zero-initialized).
// One warp = 128 contiguous edges; thread owns 4 columns (2 bf16x2 pairs).
// ---------------------------------------------------------------------------
#define EDGE_SPAN 128

__global__ void __launch_bounds__(256)
edge_kernel(const uint2* __restrict__ Pr,          // rows of 32 uint2 (128 bf16)
            const float4* __restrict__ add,
            const int* __restrict__ nidx, const int* __restrict__ segs,
            const float* __restrict__ Wadd, float* __restrict__ pool, int E)
{
    int gw = blockIdx.x * 8 + (threadIdx.x >> 5);
    int lane = threadIdx.x & 31;
    long e0 = (long)gw * EDGE_SPAN;
    if (e0 >= E) return;
    long e1 = e0 + EDGE_SPAN;
    if (e1 > E) e1 = E;

    int cb = lane * 4;
    __nv_bfloat162 wa2[4][2];
#pragma unroll
    for (int a = 0; a < 4; a++)
#pragma unroll
        for (int p = 0; p < 2; p++)
            wa2[a][p] = __floats2bfloat162_rn(__ldg(Wadd + a * 128 + cb + 2 * p),
                                              __ldg(Wadd + a * 128 + cb + 2 * p + 1));

    __nv_bfloat162 z2 = __floats2bfloat162_rn(0.f, 0.f);
    __nv_bfloat162 m0 = z2, m1 = z2;
    int cur = __ldg(segs + e0);

#define EDGE_FLUSH() do { \
    unsigned* _d = reinterpret_cast<unsigned*>(pool + (size_t)cur * 128 + cb); \
    atomicMax(_d + 0, __float_as_uint(__low2float(m0)));  \
    atomicMax(_d + 1, __float_as_uint(__high2float(m0))); \
    atomicMax(_d + 2, __float_as_uint(__low2float(m1)));  \
    atomicMax(_d + 3, __float_as_uint(__high2float(m1))); \
    m0 = z2; m1 = z2; } while (0)

#pragma unroll 4
    for (long e = e0; e < e1; ++e) {
        int    sg = __ldg(segs + e);
        int    id = __ldg(nidx + e);
        float4 ad = __ldg(add + e);
        uint2  pv = __ldg(Pr + (size_t)id * 32 + lane);
        if (sg != cur) { EDGE_FLUSH(); cur = sg; }
        __nv_bfloat162 h0 = *reinterpret_cast<__nv_bfloat162*>(&pv.x);
        __nv_bfloat162 h1 = *reinterpret_cast<__nv_bfloat162*>(&pv.y);
        __nv_bfloat162 ax = __float2bfloat162_rn(ad.x);
        __nv_bfloat162 ay = __float2bfloat162_rn(ad.y);
        __nv_bfloat162 az = __float2bfloat162_rn(ad.z);
        __nv_bfloat162 aw = __float2bfloat162_rn(ad.w);
        h0 = __hfma2(ax, wa2[0][0], h0);
        h0 = __hfma2(ay, wa2[1][0], h0);
        h0 = __hfma2(az, wa2[2][0], h0);
        h0 = __hfma2(aw, wa2[3][0], h0);
        h1 = __hfma2(ax, wa2[0][1], h1);
        h1 = __hfma2(ay, wa2[1][1], h1);
        h1 = __hfma2(az, wa2[2][1], h1);
        h1 = __hfma2(aw, wa2[3][1], h1);
        m0 = __hmax2(m0, h0);
        m1 = __hmax2(m1, h1);
    }
    EDGE_FLUSH();
#undef EDGE_FLUSH
}

// ---------------------------------------------------------------------------
extern "C" void kernel_launch(void* const* d_in, const int* in_sizes, int n_in,
                              void* d_out, int out_size)
{
    const float* interp = (const float*)d_in[0];
    const float* add    = (const float*)d_in[1];
    const int*   nidx   = (const int*)d_in[2];
    const int*   segs   = (const int*)d_in[3];
    const float* Wb0 = (const float*)d_in[4];
    const float* bb0 = (const float*)d_in[5];
    const float* Wo0 = (const float*)d_in[6];
    const float* bo0 = (const float*)d_in[7];
    const float* Wb1 = (const float*)d_in[8];
    const float* bb1 = (const float*)d_in[9];
    const float* Wo1 = (const float*)d_in[10];
    const float* bo1 = (const float*)d_in[11];
    const float* Wf  = (const float*)d_in[12];
    const float* bf  = (const float*)d_in[13];
    float* out = (float*)d_out;

    int N = in_sizes[0] / 128;
    int E = in_sizes[2];

    __nv_bfloat16 *P, *Wt;
    float *pool, *x1;
    cudaGetSymbolAddress((void**)&P, g_P);
    cudaGetSymbolAddress((void**)&pool, g_pool);
    cudaGetSymbolAddress((void**)&x1, g_x1);
    cudaGetSymbolAddress((void**)&Wt, g_Wt);

    cudaFuncSetAttribute(gemm128, cudaFuncAttributeMaxDynamicSharedMemorySize,
                         SMEM_GEMM_TOTAL);

    int gtiles = (N + 127) / 128;
    int egrid = ((E + EDGE_SPAN - 1) / EDGE_SPAN + 7) / 8;

    prep_w<<<dim3(64, 4), 256>>>(Wb0, Wo0, Wb1, Wo1, Wt);

    // Block 0
    gemm128<<<gtiles, 256, SMEM_GEMM_TOTAL>>>(interp, Wt + 0 * 16384, bb0,
        nullptr, P, nullptr, pool, nullptr, nullptr, nullptr, N, 0);
    edge_kernel<<<egrid, 256>>>((const uint2*)P, (const float4*)add, nidx, segs,
                                Wb0 + 128 * 128, pool, E);
    gemm128<<<gtiles, 256, SMEM_GEMM_TOTAL>>>(pool, Wt + 1 * 16384, bo0,
        interp, nullptr, x1, nullptr, nullptr, nullptr, nullptr, N, 1);
    // Block 1
    gemm128<<<gtiles, 256, SMEM_GEMM_TOTAL>>>(x1, Wt + 2 * 16384, bb1,
        nullptr, P, nullptr, pool, nullptr, nullptr, nullptr, N, 0);
    edge_kernel<<<egrid, 256>>>((const uint2*)P, (const float4*)add, nidx, segs,
                                Wb1 + 128 * 128, pool, E);
    // Block-1 projection + final head fused
    gemm128<<<gtiles, 256, SMEM_GEMM_TOTAL>>>(pool, Wt + 3 * 16384, bo1,
        x1, nullptr, nullptr, nullptr, Wf, bf, out, N, 2);
}

// round 4
// speedup vs baseline: 1.6813x; 1.6750x over previous
#include <cuda_runtime.h>
#include <cuda_bf16.h>
#include <cstdint>

// ---------------------------------------------------------------------------
// Problem shape (fixed by dataset): N=50000, E=1.6M, D=128, A=4, H=128
// ---------------------------------------------------------------------------
#define NMAX 50048          // 782 tiles of 64
#define EMAX 1700000
#define DDIM 128

__device__ __nv_bfloat16 g_P[(size_t)NMAX * DDIM];      // bf16 activations
__device__ float g_pool[(size_t)NMAX * DDIM];
__device__ float g_x1  [(size_t)NMAX * DDIM];
__device__ __nv_bfloat16 g_Wt[4 * 128 * 128];           // transposed bf16 weights
__device__ uint4 g_edge[EMAX];                          // packed {seg,idx,bf16 add x4}

// ---------------------------------------------------------------------------
// helpers
// ---------------------------------------------------------------------------
__device__ __forceinline__ uint32_t smem_u32(const void* p) {
    uint32_t a;
    asm("{ .reg .u64 t; cvta.to.shared.u64 t, %1; cvt.u32.u64 %0, t; }"
        : "=r"(a) : "l"(p));
    return a;
}
__device__ __forceinline__ void ldsm_x4(uint32_t& r0, uint32_t& r1,
                                        uint32_t& r2, uint32_t& r3, uint32_t a) {
    asm volatile("ldmatrix.sync.aligned.m8n8.x4.shared.b16 {%0,%1,%2,%3}, [%4];"
                 : "=r"(r0), "=r"(r1), "=r"(r2), "=r"(r3) : "r"(a));
}
__device__ __forceinline__ void ldsm_x2(uint32_t& r0, uint32_t& r1, uint32_t a) {
    asm volatile("ldmatrix.sync.aligned.m8n8.x2.shared.b16 {%0,%1}, [%2];"
                 : "=r"(r0), "=r"(r1) : "r"(a));
}
__device__ __forceinline__ void mma_bf16(float* c, const uint32_t* a, const uint32_t* b) {
    asm volatile(
        "mma.sync.aligned.m16n8k16.row.col.f32.bf16.bf16.f32 "
        "{%0,%1,%2,%3}, {%4,%5,%6,%7}, {%8,%9}, {%0,%1,%2,%3};"
        : "+f"(c[0]), "+f"(c[1]), "+f"(c[2]), "+f"(c[3])
        : "r"(a[0]), "r"(a[1]), "r"(a[2]), "r"(a[3]), "r"(b[0]), "r"(b[1]));
}

// ---------------------------------------------------------------------------
// Tiling constants: CTA = 64 rows x 128 cols, 8 warps (2 m x 4 n), K=128
// ---------------------------------------------------------------------------
#define BSTR 136                              // bf16 elems per smem row (pad 8)
static constexpr int SMEM_A  = 64 * BSTR * 2;    // 17408
static constexpr int SMEM_B  = 128 * BSTR * 2;   // 34816
static constexpr int SMEM_PF = SMEM_A + SMEM_B;          // 52224 (pre/fin)
static constexpr int SMEM_MID = SMEM_A + 2 * SMEM_B;     // 87040 (mid)

// A tile fill: 64x128 fp32 -> bf16 smem
__device__ __forceinline__ void fill_A(char* smem, const float* __restrict__ A,
                                       int tile0, int M, int tid) {
#pragma unroll
    for (int it = 0; it < 8; it++) {
        int p = it * 256 + tid;               // 0..2047
        int r = p >> 5, c = p & 31;
        int gr = tile0 + r;
        float4 v = make_float4(0.f, 0.f, 0.f, 0.f);
        if (gr < M) v = __ldg(reinterpret_cast<const float4*>(A + (size_t)gr * 128) + c);
        __nv_bfloat162 lo = __floats2bfloat162_rn(v.x, v.y);
        __nv_bfloat162 hi = __floats2bfloat162_rn(v.z, v.w);
        uint2 o = make_uint2(*reinterpret_cast<uint32_t*>(&lo),
                             *reinterpret_cast<uint32_t*>(&hi));
        *reinterpret_cast<uint2*>(smem + r * (BSTR * 2) + c * 8) = o;
    }
}
// B tile fill: 128x128 bf16 (pre-transposed) -> smem, uint4 copies
__device__ __forceinline__ void fill_B(char* dst, const __nv_bfloat16* __restrict__ Wt,
                                       int tid) {
    const uint4* src = reinterpret_cast<const uint4*>(Wt);
#pragma unroll
    for (int it = 0; it < 8; it++) {
        int p = it * 256 + tid;               // 0..2047
        int n = p >> 4, c = p & 15;
        *reinterpret_cast<uint4*>(dst + n * (BSTR * 2) + c * 16) = src[p];
    }
}
__device__ __forceinline__ void zero_pool(float* __restrict__ pool,
                                          int tile0, int M, int tid) {
#pragma unroll
    for (int it = 0; it < 8; it++) {
        int p = it * 256 + tid;
        int r = p >> 5, c = p & 31;
        if (tile0 + r < M)
            reinterpret_cast<float4*>(pool + (size_t)(tile0 + r) * 128)[c] =
                make_float4(0.f, 0.f, 0.f, 0.f);
    }
}
// MMA core: acc[2][4][4] over 64x128 tile
__device__ __forceinline__ void mma_tile(uint32_t sA, uint32_t sB,
                                         float acc[2][4][4], int lane,
                                         int wm, int wn) {
    int aRow = wm * 32 + (lane & 15);
    int aCol = (lane >> 4) * 8;
    int bRow = wn * 32 + (lane & 7);
    int bCol = ((lane >> 3) & 1) * 8;
#pragma unroll
    for (int k = 0; k < 8; k++) {
        uint32_t a[2][4], b[4][2];
#pragma unroll
        for (int mt = 0; mt < 2; mt++)
            ldsm_x4(a[mt][0], a[mt][1], a[mt][2], a[mt][3],
                    sA + (aRow + mt * 16) * (BSTR * 2) + (k * 16 + aCol) * 2);
#pragma unroll
        for (int nt = 0; nt < 4; nt++)
            ldsm_x2(b[nt][0], b[nt][1],
                    sB + (bRow + nt * 8) * (BSTR * 2) + (k * 16 + bCol) * 2);
#pragma unroll
        for (int mt = 0; mt < 2; mt++)
#pragma unroll
            for (int nt = 0; nt < 4; nt++)
                mma_bf16(acc[mt][nt], a[mt], b[nt]);
    }
}

// ---------------------------------------------------------------------------
// prep: Wt[w][n][k] = bf16(W_w[k][n])
// ---------------------------------------------------------------------------
__global__ void __launch_bounds__(256)
prep_w(const float* __restrict__ W0, const float* __restrict__ W1,
       const float* __restrict__ W2, const float* __restrict__ W3,
       __nv_bfloat16* __restrict__ Wt)
{
    const float* Ws[4] = {W0, W1, W2, W3};
    const float* W = Ws[blockIdx.y];
    __nv_bfloat16* dst = Wt + (size_t)blockIdx.y * 16384;
    int i = blockIdx.x * 256 + threadIdx.x;
    int n = i >> 7, k = i & 127;
    dst[n * 128 + k] = __float2bfloat16(W[k * 128 + n]);
}

// prep: pack per-edge metadata {seg, idx, bf16(add.xy), bf16(add.zw)}
__global__ void __launch_bounds__(256)
prep_edge(const int* __restrict__ segs, const int* __restrict__ nidx,
          const float4* __restrict__ add, uint4* __restrict__ em, int E)
{
    int i = blockIdx.x * 256 + threadIdx.x;
    if (i >= E) return;
    float4 ad = __ldg(add + i);
    __nv_bfloat162 lo = __floats2bfloat162_rn(ad.x, ad.y);
    __nv_bfloat162 hi = __floats2bfloat162_rn(ad.z, ad.w);
    em[i] = make_uint4((uint32_t)__ldg(segs + i), (uint32_t)__ldg(nidx + i),
                       *reinterpret_cast<uint32_t*>(&lo),
                       *reinterpret_cast<uint32_t*>(&hi));
}

// ---------------------------------------------------------------------------
// GEMM kernels
// ---------------------------------------------------------------------------
// pre: Pb = bf16(A@W + bias); zero pool
__global__ void __launch_bounds__(256, 3)
gemm_pre(const float* __restrict__ A, const __nv_bfloat16* __restrict__ Wt,
         const float* __restrict__ bias, __nv_bfloat16* __restrict__ Pb,
         float* __restrict__ pool, int M)
{
    extern __shared__ char smem[];
    uint32_t sA = smem_u32(smem), sB = sA + SMEM_A;
    int tid = threadIdx.x, lane = tid & 31, wid = tid >> 5;
    int wm = wid & 1, wn = wid >> 1, g = lane >> 2, tg = lane & 3;
    int tile0 = blockIdx.x * 64;

    fill_A(smem, A, tile0, M, tid);
    fill_B(smem + SMEM_A, Wt, tid);
    zero_pool(pool, tile0, M, tid);
    __syncthreads();

    float acc[2][4][4];
#pragma unroll
    for (int mt = 0; mt < 2; mt++)
#pragma unroll
        for (int nt = 0; nt < 4; nt++)
#pragma unroll
            for (int j = 0; j < 4; j++) acc[mt][nt][j] = 0.f;
    mma_tile(sA, sB, acc, lane, wm, wn);

#pragma unroll
    for (int mt = 0; mt < 2; mt++) {
        int r0 = tile0 + wm * 32 + mt * 16 + g;
#pragma unroll
        for (int nt = 0; nt < 4; nt++) {
            int c0 = wn * 32 + nt * 8 + tg * 2;
            float b0 = __ldg(bias + c0), b1 = __ldg(bias + c0 + 1);
            if (r0 < M) {
                __nv_bfloat162 o = __floats2bfloat162_rn(acc[mt][nt][0] + b0,
                                                         acc[mt][nt][1] + b1);
                *reinterpret_cast<uint32_t*>(Pb + (size_t)r0 * 128 + c0) =
                    *reinterpret_cast<uint32_t*>(&o);
            }
            if (r0 + 8 < M) {
                __nv_bfloat162 o = __floats2bfloat162_rn(acc[mt][nt][2] + b0,
                                                         acc[mt][nt][3] + b1);
                *reinterpret_cast<uint32_t*>(Pb + (size_t)(r0 + 8) * 128 + c0) =
                    *reinterpret_cast<uint32_t*>(&o);
            }
        }
    }
}

// mid: x1 = interp + pool@W1 + bo0  (fp32 out); then Pb = bf16(x1@W2 + bb1);
//      zero pool (row-local, safe after phase A consumed this tile's rows)
__global__ void __launch_bounds__(256, 2)
gemm_mid(const float* __restrict__ pool, const __nv_bfloat16* __restrict__ Wt1,
         const float* __restrict__ bo0, const float* __restrict__ interp,
         float* __restrict__ x1, const __nv_bfloat16* __restrict__ Wt2,
         const float* __restrict__ bb1, __nv_bfloat16* __restrict__ Pb,
         float* __restrict__ poolz, int M)
{
    extern __shared__ char smem[];
    uint32_t sA = smem_u32(smem), sB1 = sA + SMEM_A, sB2 = sB1 + SMEM_B;
    int tid = threadIdx.x, lane = tid & 31, wid = tid >> 5;
    int wm = wid & 1, wn = wid >> 1, g = lane >> 2, tg = lane & 3;
    int tile0 = blockIdx.x * 64;

    fill_A(smem, pool, tile0, M, tid);
    fill_B(smem + SMEM_A, Wt1, tid);
    fill_B(smem + SMEM_A + SMEM_B, Wt2, tid);
    __syncthreads();

    float acc[2][4][4];
#pragma unroll
    for (int mt = 0; mt < 2; mt++)
#pragma unroll
        for (int nt = 0; nt < 4; nt++)
#pragma unroll
            for (int j = 0; j < 4; j++) acc[mt][nt][j] = 0.f;
    mma_tile(sA, sB1, acc, lane, wm, wn);
    __syncthreads();                        // all reads of A done before overwrite

    // Phase-A epilogue: x1 = resid + acc + bias; store fp32 to gmem and bf16 to A smem
#pragma unroll
    for (int mt = 0; mt < 2; mt++) {
        int rl = wm * 32 + mt * 16 + g;
        int r0 = tile0 + rl;
#pragma unroll
        for (int nt = 0; nt < 4; nt++) {
            int c0 = wn * 32 + nt * 8 + tg * 2;
            float b0 = __ldg(bo0 + c0), b1 = __ldg(bo0 + c0 + 1);
            if (r0 < M) {
                float2 rv = *reinterpret_cast<const float2*>(
                    interp + (size_t)r0 * 128 + c0);
                float v0 = acc[mt][nt][0] + b0 + rv.x;
                float v1 = acc[mt][nt][1] + b1 + rv.y;
                *reinterpret_cast<float2*>(x1 + (size_t)r0 * 128 + c0) =
                    make_float2(v0, v1);
                __nv_bfloat162 o = __floats2bfloat162_rn(v0, v1);
                *reinterpret_cast<uint32_t*>(smem + rl * (BSTR * 2) + c0 * 2) =
                    *reinterpret_cast<uint32_t*>(&o);
            }
            if (r0 + 8 < M) {
                float2 rv = *reinterpret_cast<const float2*>(
                    interp + (size_t)(r0 + 8) * 128 + c0);
                float v0 = acc[mt][nt][2] + b0 + rv.x;
                float v1 = acc[mt][nt][3] + b1 + rv.y;
                *reinterpret_cast<float2*>(x1 + (size_t)(r0 + 8) * 128 + c0) =
                    make_float2(v0, v1);
                __nv_bfloat162 o = __floats2bfloat162_rn(v0, v1);
                *reinterpret_cast<uint32_t*>(smem + (rl + 8) * (BSTR * 2) + c0 * 2) =
                    *reinterpret_cast<uint32_t*>(&o);
            }
        }
    }
    zero_pool(poolz, tile0, M, tid);
    __syncthreads();

    // Phase B: Pb = bf16(x1@W2 + bb1)
#pragma unroll
    for (int mt = 0; mt < 2; mt++)
#pragma unroll
        for (int nt = 0; nt < 4; nt++)
#pragma unroll
            for (int j = 0; j < 4; j++) acc[mt][nt][j] = 0.f;
    mma_tile(sA, sB2, acc, lane, wm, wn);

#pragma unroll
    for (int mt = 0; mt < 2; mt++) {
        int r0 = tile0 + wm * 32 + mt * 16 + g;
#pragma unroll
        for (int nt = 0; nt < 4; nt++) {
            int c0 = wn * 32 + nt * 8 + tg * 2;
            float b0 = __ldg(bb1 + c0), b1 = __ldg(bb1 + c0 + 1);
            if (r0 < M) {
                __nv_bfloat162 o = __floats2bfloat162_rn(acc[mt][nt][0] + b0,
                                                         acc[mt][nt][1] + b1);
                *reinterpret_cast<uint32_t*>(Pb + (size_t)r0 * 128 + c0) =
                    *reinterpret_cast<uint32_t*>(&o);
            }
            if (r0 + 8 < M) {
                __nv_bfloat162 o = __floats2bfloat162_rn(acc[mt][nt][2] + b0,
                                                         acc[mt][nt][3] + b1);
                *reinterpret_cast<uint32_t*>(Pb + (size_t)(r0 + 8) * 128 + c0) =
                    *reinterpret_cast<uint32_t*>(&o);
            }
        }
    }
}

// fin: out = (x1 + pool@W3 + bo1) @ Wf + bf
__global__ void __launch_bounds__(256, 3)
gemm_fin(const float* __restrict__ pool, const __nv_bfloat16* __restrict__ Wt3,
         const float* __restrict__ bo1, const float* __restrict__ x1,
         const float* __restrict__ Wf, const float* __restrict__ bfp,
         float* __restrict__ out, int M)
{
    extern __shared__ char smem[];
    uint32_t sA = smem_u32(smem), sB = sA + SMEM_A;
    int tid = threadIdx.x, lane = tid & 31, wid = tid >> 5;
    int wm = wid & 1, wn = wid >> 1, g = lane >> 2, tg = lane & 3;
    int tile0 = blockIdx.x * 64;

    fill_A(smem, pool, tile0, M, tid);
    fill_B(smem + SMEM_A, Wt3, tid);
    __syncthreads();

    float acc[2][4][4];
#pragma unroll
    for (int mt = 0; mt < 2; mt++)
#pragma unroll
        for (int nt = 0; nt < 4; nt++)
#pragma unroll
            for (int j = 0; j < 4; j++) acc[mt][nt][j] = 0.f;
    mma_tile(sA, sB, acc, lane, wm, wn);
    __syncthreads();                        // done with A/B smem -> reuse for hp

    float* hp = reinterpret_cast<float*>(smem);   // [64][17]
#pragma unroll
    for (int mt = 0; mt < 2; mt++) {
        int rl = wm * 32 + mt * 16 + g;
        int r0 = tile0 + rl;
        float plo = 0.f, phi = 0.f;
#pragma unroll
        for (int nt = 0; nt < 4; nt++) {
            int c0 = wn * 32 + nt * 8 + tg * 2;
            float b0 = __ldg(bo1 + c0), b1 = __ldg(bo1 + c0 + 1);
            float w0 = __ldg(Wf + c0),  w1 = __ldg(Wf + c0 + 1);
            float v0 = acc[mt][nt][0] + b0, v1 = acc[mt][nt][1] + b1;
            float u0 = acc[mt][nt][2] + b0, u1 = acc[mt][nt][3] + b1;
            if (r0 < M) {
                float2 rv = *reinterpret_cast<const float2*>(
                    x1 + (size_t)r0 * 128 + c0);
                plo += (v0 + rv.x) * w0 + (v1 + rv.y) * w1;
            }
            if (r0 + 8 < M) {
                float2 rv = *reinterpret_cast<const float2*>(
                    x1 + (size_t)(r0 + 8) * 128 + c0);
                phi += (u0 + rv.x) * w0 + (u1 + rv.y) * w1;
            }
        }
        hp[rl * 17 + wn * 4 + tg] = plo;
        hp[(rl + 8) * 17 + wn * 4 + tg] = phi;
    }
    __syncthreads();
    if (tid < 64) {
        int r0 = tile0 + tid;
        if (r0 < M) {
            float s = 0.f;
#pragma unroll
            for (int j = 0; j < 16; j++) s += hp[tid * 17 + j];
            out[r0] = s + __ldg(bfp);
        }
    }
}

// ---------------------------------------------------------------------------
// Edge kernel: packed meta uint4 {seg, idx, add bf16x4}; h2 = P2[idx] + add@Wadd
// (HFMA2); relu folded into zero-init running max (HMAX2); flush via fp32
// atomicMax-on-uint (valid: values >= 0, pool zero-initialized).
// One warp = 128 contiguous edges; thread owns 4 columns (2 bf16x2 pairs).
// ---------------------------------------------------------------------------
#define EDGE_SPAN 128

__global__ void __launch_bounds__(256)
edge_kernel(const uint2* __restrict__ Pr, const uint4* __restrict__ em,
            const float* __restrict__ Wadd, float* __restrict__ pool, int E)
{
    int gw = blockIdx.x * 8 + (threadIdx.x >> 5);
    int lane = threadIdx.x & 31;
    long e0 = (long)gw * EDGE_SPAN;
    if (e0 >= E) return;
    long e1 = e0 + EDGE_SPAN;
    if (e1 > E) e1 = E;

    int cb = lane * 4;
    __nv_bfloat162 wa2[4][2];
#pragma unroll
    for (int a = 0; a < 4; a++)
#pragma unroll
        for (int p = 0; p < 2; p++)
            wa2[a][p] = __floats2bfloat162_rn(__ldg(Wadd + a * 128 + cb + 2 * p),
                                              __ldg(Wadd + a * 128 + cb + 2 * p + 1));

    __nv_bfloat162 z2 = __floats2bfloat162_rn(0.f, 0.f);
    __nv_bfloat162 m0 = z2, m1 = z2;
    int cur = (int)__ldg(reinterpret_cast<const uint32_t*>(em + e0));

#define EDGE_FLUSH() do { \
    unsigned* _d = reinterpret_cast<unsigned*>(pool + (size_t)cur * 128 + cb); \
    atomicMax(_d + 0, __float_as_uint(__low2float(m0)));  \
    atomicMax(_d + 1, __float_as_uint(__high2float(m0))); \
    atomicMax(_d + 2, __float_as_uint(__low2float(m1)));  \
    atomicMax(_d + 3, __float_as_uint(__high2float(m1))); \
    m0 = z2; m1 = z2; } while (0)

#pragma unroll 4
    for (long e = e0; e < e1; ++e) {
        uint4 md = __ldg(em + e);
        int sg = (int)md.x;
        uint2 pv = __ldg(Pr + (size_t)md.y * 32 + lane);
        if (sg != cur) { EDGE_FLUSH(); cur = sg; }
        __nv_bfloat162 h0 = *reinterpret_cast<__nv_bfloat162*>(&pv.x);
        __nv_bfloat162 h1 = *reinterpret_cast<__nv_bfloat162*>(&pv.y);
        __nv_bfloat162 axy = *reinterpret_cast<__nv_bfloat162*>(&md.z);
        __nv_bfloat162 azw = *reinterpret_cast<__nv_bfloat162*>(&md.w);
        __nv_bfloat162 ax = __low2bfloat162(axy),  ay = __high2bfloat162(axy);
        __nv_bfloat162 az = __low2bfloat162(azw),  aw = __high2bfloat162(azw);
        h0 = __hfma2(ax, wa2[0][0], h0);
        h0 = __hfma2(ay, wa2[1][0], h0);
        h0 = __hfma2(az, wa2[2][0], h0);
        h0 = __hfma2(aw, wa2[3][0], h0);
        h1 = __hfma2(ax, wa2[0][1], h1);
        h1 = __hfma2(ay, wa2[1][1], h1);
        h1 = __hfma2(az, wa2[2][1], h1);
        h1 = __hfma2(aw, wa2[3][1], h1);
        m0 = __hmax2(m0, h0);
        m1 = __hmax2(m1, h1);
    }
    EDGE_FLUSH();
#undef EDGE_FLUSH
}

// ---------------------------------------------------------------------------
extern "C" void kernel_launch(void* const* d_in, const int* in_sizes, int n_in,
                              void* d_out, int out_size)
{
    const float* interp = (const float*)d_in[0];
    const float* add    = (const float*)d_in[1];
    const int*   nidx   = (const int*)d_in[2];
    const int*   segs   = (const int*)d_in[3];
    const float* Wb0 = (const float*)d_in[4];
    const float* bb0 = (const float*)d_in[5];
    const float* Wo0 = (const float*)d_in[6];
    const float* bo0 = (const float*)d_in[7];
    const float* Wb1 = (const float*)d_in[8];
    const float* bb1 = (const float*)d_in[9];
    const float* Wo1 = (const float*)d_in[10];
    const float* bo1 = (const float*)d_in[11];
    const float* Wf  = (const float*)d_in[12];
    const float* bf  = (const float*)d_in[13];
    float* out = (float*)d_out;

    int N = in_sizes[0] / 128;
    int E = in_sizes[2];

    __nv_bfloat16 *P, *Wt;
    float *pool, *x1;
    uint4* em;
    cudaGetSymbolAddress((void**)&P, g_P);
    cudaGetSymbolAddress((void**)&pool, g_pool);
    cudaGetSymbolAddress((void**)&x1, g_x1);
    cudaGetSymbolAddress((void**)&Wt, g_Wt);
    cudaGetSymbolAddress((void**)&em, g_edge);

    cudaFuncSetAttribute(gemm_pre, cudaFuncAttributeMaxDynamicSharedMemorySize, SMEM_PF);
    cudaFuncSetAttribute(gemm_mid, cudaFuncAttributeMaxDynamicSharedMemorySize, SMEM_MID);
    cudaFuncSetAttribute(gemm_fin, cudaFuncAttributeMaxDynamicSharedMemorySize, SMEM_PF);

    int gtiles = (N + 63) / 64;
    int egrid = ((E + EDGE_SPAN - 1) / EDGE_SPAN + 7) / 8;

    prep_w<<<dim3(64, 4), 256>>>(Wb0, Wo0, Wb1, Wo1, Wt);
    prep_edge<<<(E + 255) / 256, 256>>>(segs, nidx, (const float4*)add, em, E);

    // Block 0
    gemm_pre<<<gtiles, 256, SMEM_PF>>>(interp, Wt + 0 * 16384, bb0, P, pool, N);
    edge_kernel<<<egrid, 256>>>((const uint2*)P, em, Wb0 + 128 * 128, pool, E);
    // Block-0 projection + Block-1 pre-edge GEMM fused (also re-zeros pool)
    gemm_mid<<<gtiles, 256, SMEM_MID>>>(pool, Wt + 1 * 16384, bo0, interp, x1,
                                        Wt + 2 * 16384, bb1, P, pool, N);
    edge_kernel<<<egrid, 256>>>((const uint2*)P, em, Wb1 + 128 * 128, pool, E);
    // Block-1 projection + final head fused
    gemm_fin<<<gtiles, 256, SMEM_PF>>>(pool, Wt + 3 * 16384, bo1, x1, Wf, bf, out, N);
}

// round 6
// speedup vs baseline: 1.8245x; 1.0852x over previous
#include <cuda_runtime.h>
#include <cuda_bf16.h>
#include <cstdint>

// ---------------------------------------------------------------------------
// Problem shape (fixed by dataset): N=50000, E=1.6M, D=128, A=4, H=128
// ---------------------------------------------------------------------------
#define NMAX 50048          // 782 tiles of 64
#define EMAX 1700000
#define DDIM 128

__device__ __nv_bfloat16 g_P[(size_t)NMAX * DDIM];      // bf16 activations (pre-edge)
__device__ __nv_bfloat16 g_poolb[(size_t)NMAX * DDIM];  // bf16 pooled output
__device__ float g_x1  [(size_t)NMAX * DDIM];           // fp32 residual stream
__device__ __nv_bfloat16 g_Wt[4 * 128 * 128];           // transposed bf16 weights
__device__ uint4 g_edge[EMAX];                          // packed {idx, bf16 add x4, 0}
__device__ int   g_start[NMAX + 1];                     // CSR segment starts

// ---------------------------------------------------------------------------
// helpers
// ---------------------------------------------------------------------------
__device__ __forceinline__ uint32_t smem_u32(const void* p) {
    uint32_t a;
    asm("{ .reg .u64 t; cvta.to.shared.u64 t, %1; cvt.u32.u64 %0, t; }"
        : "=r"(a) : "l"(p));
    return a;
}
__device__ __forceinline__ void ldsm_x4(uint32_t& r0, uint32_t& r1,
                                        uint32_t& r2, uint32_t& r3, uint32_t a) {
    asm volatile("ldmatrix.sync.aligned.m8n8.x4.shared.b16 {%0,%1,%2,%3}, [%4];"
                 : "=r"(r0), "=r"(r1), "=r"(r2), "=r"(r3) : "r"(a));
}
__device__ __forceinline__ void ldsm_x2(uint32_t& r0, uint32_t& r1, uint32_t a) {
    asm volatile("ldmatrix.sync.aligned.m8n8.x2.shared.b16 {%0,%1}, [%2];"
                 : "=r"(r0), "=r"(r1) : "r"(a));
}
__device__ __forceinline__ void mma_bf16(float* c, const uint32_t* a, const uint32_t* b) {
    asm volatile(
        "mma.sync.aligned.m16n8k16.row.col.f32.bf16.bf16.f32 "
        "{%0,%1,%2,%3}, {%4,%5,%6,%7}, {%8,%9}, {%0,%1,%2,%3};"
        : "+f"(c[0]), "+f"(c[1]), "+f"(c[2]), "+f"(c[3])
        : "r"(a[0]), "r"(a[1]), "r"(a[2]), "r"(a[3]), "r"(b[0]), "r"(b[1]));
}

// ---------------------------------------------------------------------------
// Tiling constants: CTA = 64 rows x 128 cols, 8 warps (2 m x 4 n), K=128
// ---------------------------------------------------------------------------
#define BSTR 136                              // bf16 elems per smem row (pad 8)
static constexpr int SMEM_A  = 64 * BSTR * 2;    // 17408
static constexpr int SMEM_B  = 128 * BSTR * 2;   // 34816
static constexpr int SMEM_PF = SMEM_A + SMEM_B;          // 52224 (pre/fin)
static constexpr int SMEM_MID = SMEM_A + 2 * SMEM_B;     // 87040 (mid)

// A tile fill: 64x128 fp32 -> bf16 smem
__device__ __forceinline__ void fill_A(char* smem, const float* __restrict__ A,
                                       int tile0, int M, int tid) {
#pragma unroll
    for (int it = 0; it < 8; it++) {
        int p = it * 256 + tid;               // 0..2047
        int r = p >> 5, c = p & 31;
        int gr = tile0 + r;
        float4 v = make_float4(0.f, 0.f, 0.f, 0.f);
        if (gr < M) v = __ldg(reinterpret_cast<const float4*>(A + (size_t)gr * 128) + c);
        __nv_bfloat162 lo = __floats2bfloat162_rn(v.x, v.y);
        __nv_bfloat162 hi = __floats2bfloat162_rn(v.z, v.w);
        uint2 o = make_uint2(*reinterpret_cast<uint32_t*>(&lo),
                             *reinterpret_cast<uint32_t*>(&hi));
        *reinterpret_cast<uint2*>(smem + r * (BSTR * 2) + c * 8) = o;
    }
}
// A tile fill from bf16 source (straight copy)
__device__ __forceinline__ void fill_Abf(char* smem, const __nv_bfloat16* __restrict__ A,
                                         int tile0, int M, int tid) {
    const uint4* src = reinterpret_cast<const uint4*>(A + (size_t)tile0 * 128);
#pragma unroll
    for (int it = 0; it < 4; it++) {
        int p = it * 256 + tid;               // 0..1023
        int r = p >> 4, c = p & 15;
        uint4 v = make_uint4(0, 0, 0, 0);
        if (tile0 + r < M) v = __ldg(src + p);
        *reinterpret_cast<uint4*>(smem + r * (BSTR * 2) + c * 16) = v;
    }
}
// B tile fill: 128x128 bf16 (pre-transposed) -> smem, uint4 copies
__device__ __forceinline__ void fill_B(char* dst, const __nv_bfloat16* __restrict__ Wt,
                                       int tid) {
    const uint4* src = reinterpret_cast<const uint4*>(Wt);
#pragma unroll
    for (int it = 0; it < 8; it++) {
        int p = it * 256 + tid;               // 0..2047
        int n = p >> 4, c = p & 15;
        *reinterpret_cast<uint4*>(dst + n * (BSTR * 2) + c * 16) = src[p];
    }
}
// MMA core: acc[2][4][4] over 64x128 tile
__device__ __forceinline__ void mma_tile(uint32_t sA, uint32_t sB,
                                         float acc[2][4][4], int lane,
                                         int wm, int wn) {
    int aRow = wm * 32 + (lane & 15);
    int aCol = (lane >> 4) * 8;
    int bRow = wn * 32 + (lane & 7);
    int bCol = ((lane >> 3) & 1) * 8;
#pragma unroll
    for (int k = 0; k < 8; k++) {
        uint32_t a[2][4], b[4][2];
#pragma unroll
        for (int mt = 0; mt < 2; mt++)
            ldsm_x4(a[mt][0], a[mt][1], a[mt][2], a[mt][3],
                    sA + (aRow + mt * 16) * (BSTR * 2) + (k * 16 + aCol) * 2);
#pragma unroll
        for (int nt = 0; nt < 4; nt++)
            ldsm_x2(b[nt][0], b[nt][1],
                    sB + (bRow + nt * 8) * (BSTR * 2) + (k * 16 + bCol) * 2);
#pragma unroll
        for (int mt = 0; mt < 2; mt++)
#pragma unroll
            for (int nt = 0; nt < 4; nt++)
                mma_bf16(acc[mt][nt], a[mt], b[nt]);
    }
}

// ---------------------------------------------------------------------------
// prep: Wt[w][n][k] = bf16(W_w[k][n])
// ---------------------------------------------------------------------------
__global__ void __launch_bounds__(256)
prep_w(const float* __restrict__ W0, const float* __restrict__ W1,
       const float* __restrict__ W2, const float* __restrict__ W3,
       __nv_bfloat16* __restrict__ Wt)
{
    const float* Ws[4] = {W0, W1, W2, W3};
    const float* W = Ws[blockIdx.y];
    __nv_bfloat16* dst = Wt + (size_t)blockIdx.y * 16384;
    int i = blockIdx.x * 256 + threadIdx.x;
    int n = i >> 7, k = i & 127;
    dst[n * 128 + k] = __float2bfloat16(W[k * 128 + n]);
}

// prep: pack per-edge meta {idx, bf16(add.xy), bf16(add.zw), 0} + CSR starts
__global__ void __launch_bounds__(256)
prep_edge(const int* __restrict__ segs, const int* __restrict__ nidx,
          const float4* __restrict__ add, uint4* __restrict__ em,
          int* __restrict__ start, int E, int N)
{
    int i = blockIdx.x * 256 + threadIdx.x;
    if (i >= E) return;
    float4 ad = __ldg(add + i);
    __nv_bfloat162 lo = __floats2bfloat162_rn(ad.x, ad.y);
    __nv_bfloat162 hi = __floats2bfloat162_rn(ad.z, ad.w);
    em[i] = make_uint4((uint32_t)__ldg(nidx + i),
                       *reinterpret_cast<uint32_t*>(&lo),
                       *reinterpret_cast<uint32_t*>(&hi), 0u);
    int b = __ldg(segs + i);
    int a = (i == 0) ? -1 : __ldg(segs + i - 1);
    for (int s = a + 1; s <= b; s++) start[s] = i;
    if (i == E - 1)
        for (int s = b + 1; s <= N; s++) start[s] = E;
}

// ---------------------------------------------------------------------------
// GEMM kernels
// ---------------------------------------------------------------------------
// pre: Pb = bf16(A@W + bias)   (A fp32)
__global__ void __launch_bounds__(256, 3)
gemm_pre(const float* __restrict__ A, const __nv_bfloat16* __restrict__ Wt,
         const float* __restrict__ bias, __nv_bfloat16* __restrict__ Pb, int M)
{
    extern __shared__ char smem[];
    uint32_t sA = smem_u32(smem), sB = sA + SMEM_A;
    int tid = threadIdx.x, lane = tid & 31, wid = tid >> 5;
    int wm = wid & 1, wn = wid >> 1, g = lane >> 2, tg = lane & 3;
    int tile0 = blockIdx.x * 64;

    fill_A(smem, A, tile0, M, tid);
    fill_B(smem + SMEM_A, Wt, tid);
    __syncthreads();

    float acc[2][4][4];
#pragma unroll
    for (int mt = 0; mt < 2; mt++)
#pragma unroll
        for (int nt = 0; nt < 4; nt++)
#pragma unroll
            for (int j = 0; j < 4; j++) acc[mt][nt][j] = 0.f;
    mma_tile(sA, sB, acc, lane, wm, wn);

#pragma unroll
    for (int mt = 0; mt < 2; mt++) {
        int r0 = tile0 + wm * 32 + mt * 16 + g;
#pragma unroll
        for (int nt = 0; nt < 4; nt++) {
            int c0 = wn * 32 + nt * 8 + tg * 2;
            float b0 = __ldg(bias + c0), b1 = __ldg(bias + c0 + 1);
            if (r0 < M) {
                __nv_bfloat162 o = __floats2bfloat162_rn(acc[mt][nt][0] + b0,
                                                         acc[mt][nt][1] + b1);
                *reinterpret_cast<uint32_t*>(Pb + (size_t)r0 * 128 + c0) =
                    *reinterpret_cast<uint32_t*>(&o);
            }
            if (r0 + 8 < M) {
                __nv_bfloat162 o = __floats2bfloat162_rn(acc[mt][nt][2] + b0,
                                                         acc[mt][nt][3] + b1);
                *reinterpret_cast<uint32_t*>(Pb + (size_t)(r0 + 8) * 128 + c0) =
                    *reinterpret_cast<uint32_t*>(&o);
            }
        }
    }
}

// mid: x1 = interp + poolb@W1 + bo0 (fp32 out); then Pb = bf16(x1@W2 + bb1)
__global__ void __launch_bounds__(256, 2)
gemm_mid(const __nv_bfloat16* __restrict__ poolb,
         const __nv_bfloat16* __restrict__ Wt1,
         const float* __restrict__ bo0, const float* __restrict__ interp,
         float* __restrict__ x1, const __nv_bfloat16* __restrict__ Wt2,
         const float* __restrict__ bb1, __nv_bfloat16* __restrict__ Pb, int M)
{
    extern __shared__ char smem[];
    uint32_t sA = smem_u32(smem), sB1 = sA + SMEM_A, sB2 = sB1 + SMEM_B;
    int tid = threadIdx.x, lane = tid & 31, wid = tid >> 5;
    int wm = wid & 1, wn = wid >> 1, g = lane >> 2, tg = lane & 3;
    int tile0 = blockIdx.x * 64;

    fill_Abf(smem, poolb, tile0, M, tid);
    fill_B(smem + SMEM_A, Wt1, tid);
    fill_B(smem + SMEM_A + SMEM_B, Wt2, tid);
    __syncthreads();

    float acc[2][4][4];
#pragma unroll
    for (int mt = 0; mt < 2; mt++)
#pragma unroll
        for (int nt = 0; nt < 4; nt++)
#pragma unroll
            for (int j = 0; j < 4; j++) acc[mt][nt][j] = 0.f;
    mma_tile(sA, sB1, acc, lane, wm, wn);
    __syncthreads();                        // all reads of A done before overwrite

    // Phase-A epilogue: x1 = resid + acc + bias; fp32 -> gmem, bf16 -> A smem
#pragma unroll
    for (int mt = 0; mt < 2; mt++) {
        int rl = wm * 32 + mt * 16 + g;
        int r0 = tile0 + rl;
#pragma unroll
        for (int nt = 0; nt < 4; nt++) {
            int c0 = wn * 32 + nt * 8 + tg * 2;
            float b0 = __ldg(bo0 + c0), b1 = __ldg(bo0 + c0 + 1);
            if (r0 < M) {
                float2 rv = *reinterpret_cast<const float2*>(
                    interp + (size_t)r0 * 128 + c0);
                float v0 = acc[mt][nt][0] + b0 + rv.x;
                float v1 = acc[mt][nt][1] + b1 + rv.y;
                *reinterpret_cast<float2*>(x1 + (size_t)r0 * 128 + c0) =
                    make_float2(v0, v1);
                __nv_bfloat162 o = __floats2bfloat162_rn(v0, v1);
                *reinterpret_cast<uint32_t*>(smem + rl * (BSTR * 2) + c0 * 2) =
                    *reinterpret_cast<uint32_t*>(&o);
            }
            if (r0 + 8 < M) {
                float2 rv = *reinterpret_cast<const float2*>(
                    interp + (size_t)(r0 + 8) * 128 + c0);
                float v0 = acc[mt][nt][2] + b0 + rv.x;
                float v1 = acc[mt][nt][3] + b1 + rv.y;
                *reinterpret_cast<float2*>(x1 + (size_t)(r0 + 8) * 128 + c0) =
                    make_float2(v0, v1);
                __nv_bfloat162 o = __floats2bfloat162_rn(v0, v1);
                *reinterpret_cast<uint32_t*>(smem + (rl + 8) * (BSTR * 2) + c0 * 2) =
                    *reinterpret_cast<uint32_t*>(&o);
            }
        }
    }
    __syncthreads();

    // Phase B: Pb = bf16(x1@W2 + bb1)
#pragma unroll
    for (int mt = 0; mt < 2; mt++)
#pragma unroll
        for (int nt = 0; nt < 4; nt++)
#pragma unroll
            for (int j = 0; j < 4; j++) acc[mt][nt][j] = 0.f;
    mma_tile(sA, sB2, acc, lane, wm, wn);

#pragma unroll
    for (int mt = 0; mt < 2; mt++) {
        int r0 = tile0 + wm * 32 + mt * 16 + g;
#pragma unroll
        for (int nt = 0; nt < 4; nt++) {
            int c0 = wn * 32 + nt * 8 + tg * 2;
            float b0 = __ldg(bb1 + c0), b1 = __ldg(bb1 + c0 + 1);
            if (r0 < M) {
                __nv_bfloat162 o = __floats2bfloat162_rn(acc[mt][nt][0] + b0,
                                                         acc[mt][nt][1] + b1);
                *reinterpret_cast<uint32_t*>(Pb + (size_t)r0 * 128 + c0) =
                    *reinterpret_cast<uint32_t*>(&o);
            }
            if (r0 + 8 < M) {
                __nv_bfloat162 o = __floats2bfloat162_rn(acc[mt][nt][2] + b0,
                                                         acc[mt][nt][3] + b1);
                *reinterpret_cast<uint32_t*>(Pb + (size_t)(r0 + 8) * 128 + c0) =
                    *reinterpret_cast<uint32_t*>(&o);
            }
        }
    }
}

// fin: out = (x1 + poolb@W3 + bo1) @ Wf + bf
__global__ void __launch_bounds__(256, 3)
gemm_fin(const __nv_bfloat16* __restrict__ poolb,
         const __nv_bfloat16* __restrict__ Wt3,
         const float* __restrict__ bo1, const float* __restrict__ x1,
         const float* __restrict__ Wf, const float* __restrict__ bfp,
         float* __restrict__ out, int M)
{
    extern __shared__ char smem[];
    uint32_t sA = smem_u32(smem), sB = sA + SMEM_A;
    int tid = threadIdx.x, lane = tid & 31, wid = tid >> 5;
    int wm = wid & 1, wn = wid >> 1, g = lane >> 2, tg = lane & 3;
    int tile0 = blockIdx.x * 64;

    fill_Abf(smem, poolb, tile0, M, tid);
    fill_B(smem + SMEM_A, Wt3, tid);
    __syncthreads();

    float acc[2][4][4];
#pragma unroll
    for (int mt = 0; mt < 2; mt++)
#pragma unroll
        for (int nt = 0; nt < 4; nt++)
#pragma unroll
            for (int j = 0; j < 4; j++) acc[mt][nt][j] = 0.f;
    mma_tile(sA, sB, acc, lane, wm, wn);
    __syncthreads();                        // done with A/B smem -> reuse for hp

    float* hp = reinterpret_cast<float*>(smem);   // [64][17]
#pragma unroll
    for (int mt = 0; mt < 2; mt++) {
        int rl = wm * 32 + mt * 16 + g;
        int r0 = tile0 + rl;
        float plo = 0.f, phi = 0.f;
#pragma unroll
        for (int nt = 0; nt < 4; nt++) {
            int c0 = wn * 32 + nt * 8 + tg * 2;
            float b0 = __ldg(bo1 + c0), b1 = __ldg(bo1 + c0 + 1);
            float w0 = __ldg(Wf + c0),  w1 = __ldg(Wf + c0 + 1);
            float v0 = acc[mt][nt][0] + b0, v1 = acc[mt][nt][1] + b1;
            float u0 = acc[mt][nt][2] + b0, u1 = acc[mt][nt][3] + b1;
            if (r0 < M) {
                float2 rv = *reinterpret_cast<const float2*>(
                    x1 + (size_t)r0 * 128 + c0);
                plo += (v0 + rv.x) * w0 + (v1 + rv.y) * w1;
            }
            if (r0 + 8 < M) {
                float2 rv = *reinterpret_cast<const float2*>(
                    x1 + (size_t)(r0 + 8) * 128 + c0);
                phi += (u0 + rv.x) * w0 + (u1 + rv.y) * w1;
            }
        }
        hp[rl * 17 + wn * 4 + tg] = plo;
        hp[(rl + 8) * 17 + wn * 4 + tg] = phi;
    }
    __syncthreads();
    if (tid < 64) {
        int r0 = tile0 + tid;
        if (r0 < M) {
            float s = 0.f;
#pragma unroll
            for (int j = 0; j < 16; j++) s += hp[tid * 17 + j];
            out[r0] = s + __ldg(bfp);
        }
    }
}

// ---------------------------------------------------------------------------
// Edge kernel (CSR): one warp per segment. For each edge of the segment:
// h2 = P2[idx] + add@Wadd (HFMA2), running max (HMAX2, zero-init = relu fold).
// Final pooled row written with a plain bf16 store — NO atomics, NO zeroing.
// Thread owns 4 columns (2 bf16x2 pairs).
// ---------------------------------------------------------------------------
__global__ void __launch_bounds__(256)
edge_kernel(const uint2* __restrict__ Pr, const uint4* __restrict__ em,
            const int* __restrict__ start, const float* __restrict__ Wadd,
            uint2* __restrict__ poolb, int N)
{
    int s = blockIdx.x * 8 + (threadIdx.x >> 5);
    if (s >= N) return;
    int lane = threadIdx.x & 31;
    int e  = __ldg(start + s);
    int en = __ldg(start + s + 1);

    int cb = lane * 4;
    __nv_bfloat162 wa2[4][2];
#pragma unroll
    for (int a = 0; a < 4; a++)
#pragma unroll
        for (int p = 0; p < 2; p++)
            wa2[a][p] = __floats2bfloat162_rn(__ldg(Wadd + a * 128 + cb + 2 * p),
                                              __ldg(Wadd + a * 128 + cb + 2 * p + 1));

    __nv_bfloat162 z2 = __floats2bfloat162_rn(0.f, 0.f);
    __nv_bfloat162 m0 = z2, m1 = z2;

#pragma unroll 2
    for (; e < en; ++e) {
        uint4 md = __ldg(em + e);
        uint2 pv = __ldg(Pr + (size_t)md.x * 32 + lane);
        __nv_bfloat162 h0 = *reinterpret_cast<__nv_bfloat162*>(&pv.x);
        __nv_bfloat162 h1 = *reinterpret_cast<__nv_bfloat162*>(&pv.y);
        __nv_bfloat162 axy = *reinterpret_cast<__nv_bfloat162*>(&md.y);
        __nv_bfloat162 azw = *reinterpret_cast<__nv_bfloat162*>(&md.z);
        __nv_bfloat162 ax = __low2bfloat162(axy),  ay = __high2bfloat162(axy);
        __nv_bfloat162 az = __low2bfloat162(azw),  aw = __high2bfloat162(azw);
        h0 = __hfma2(ax, wa2[0][0], h0);
        h0 = __hfma2(ay, wa2[1][0], h0);
        h0 = __hfma2(az, wa2[2][0], h0);
        h0 = __hfma2(aw, wa2[3][0], h0);
        h1 = __hfma2(ax, wa2[0][1], h1);
        h1 = __hfma2(ay, wa2[1][1], h1);
        h1 = __hfma2(az, wa2[2][1], h1);
        h1 = __hfma2(aw, wa2[3][1], h1);
        m0 = __hmax2(m0, h0);
        m1 = __hmax2(m1, h1);
    }
    uint2 o;
    o.x = *reinterpret_cast<uint32_t*>(&m0);
    o.y = *reinterpret_cast<uint32_t*>(&m1);
    poolb[(size_t)s * 32 + lane] = o;
}

// ---------------------------------------------------------------------------
extern "C" void kernel_launch(void* const* d_in, const int* in_sizes, int n_in,
                              void* d_out, int out_size)
{
    const float* interp = (const float*)d_in[0];
    const float* add    = (const float*)d_in[1];
    const int*   nidx   = (const int*)d_in[2];
    const int*   segs   = (const int*)d_in[3];
    const float* Wb0 = (const float*)d_in[4];
    const float* bb0 = (const float*)d_in[5];
    const float* Wo0 = (const float*)d_in[6];
    const float* bo0 = (const float*)d_in[7];
    const float* Wb1 = (const float*)d_in[8];
    const float* bb1 = (const float*)d_in[9];
    const float* Wo1 = (const float*)d_in[10];
    const float* bo1 = (const float*)d_in[11];
    const float* Wf  = (const float*)d_in[12];
    const float* bf  = (const float*)d_in[13];
    float* out = (float*)d_out;

    int N = in_sizes[0] / 128;
    int E = in_sizes[2];

    __nv_bfloat16 *P, *poolb, *Wt;
    float *x1;
    uint4* em;
    int* start;
    cudaGetSymbolAddress((void**)&P, g_P);
    cudaGetSymbolAddress((void**)&poolb, g_poolb);
    cudaGetSymbolAddress((void**)&x1, g_x1);
    cudaGetSymbolAddress((void**)&Wt, g_Wt);
    cudaGetSymbolAddress((void**)&em, g_edge);
    cudaGetSymbolAddress((void**)&start, g_start);

    cudaFuncSetAttribute(gemm_pre, cudaFuncAttributeMaxDynamicSharedMemorySize, SMEM_PF);
    cudaFuncSetAttribute(gemm_mid, cudaFuncAttributeMaxDynamicSharedMemorySize, SMEM_MID);
    cudaFuncSetAttribute(gemm_fin, cudaFuncAttributeMaxDynamicSharedMemorySize, SMEM_PF);

    int gtiles = (N + 63) / 64;
    int sgrid = (N + 7) / 8;

    prep_w<<<dim3(64, 4), 256>>>(Wb0, Wo0, Wb1, Wo1, Wt);
    prep_edge<<<(E + 255) / 256, 256>>>(segs, nidx, (const float4*)add, em,
                                        start, E, N);

    // Block 0
    gemm_pre<<<gtiles, 256, SMEM_PF>>>(interp, Wt + 0 * 16384, bb0, P, N);
    edge_kernel<<<sgrid, 256>>>((const uint2*)P, em, start, Wb0 + 128 * 128,
                                (uint2*)poolb, N);
    // Block-0 projection + Block-1 pre-edge GEMM fused
    gemm_mid<<<gtiles, 256, SMEM_MID>>>(poolb, Wt + 1 * 16384, bo0, interp, x1,
                                        Wt + 2 * 16384, bb1, P, N);
    edge_kernel<<<sgrid, 256>>>((const uint2*)P, em, start, Wb1 + 128 * 128,
                                (uint2*)poolb, N);
    // Block-1 projection + final head fused
    gemm_fin<<<gtiles, 256, SMEM_PF>>>(poolb, Wt + 3 * 16384, bo1, x1, Wf, bf,
                                       out, N);
}